// round 6
// baseline (speedup 1.0000x reference)
#include <cuda_runtime.h>
#include <cuda_bf16.h>

// BodyKinematics tree FK. B=4096, N=256, E=255.
// Round 6: single kernel. Per-CTA cooperative coalesced staging of tip (into
// the same smem array the tree reuses for worlds) and la; closed-form
// Rx*Ry*Rz locals; 7-level tree; coalesced 16KB block output.

#define NN 256
#define EE 255
#define PI_F 3.14159265358979f

__device__ __forceinline__ float ftanh(float x) {
    float ax = fabsf(x);
    float t = __expf(2.0f * ax);
    float r = __fdividef(t - 1.0f, t + 1.0f);
    r = ax > 40.0f ? 1.0f : r;
    return copysignf(r, x);
}

// world_row = P.x*L0 + P.y*L1 + P.z*L2 (+ P.w in translation slot)
__device__ __forceinline__ float4 aff(float4 P, float4 L0, float4 L1, float4 L2) {
    float4 w;
    w.x = fmaf(P.x, L0.x, fmaf(P.y, L1.x, P.z * L2.x));
    w.y = fmaf(P.x, L0.y, fmaf(P.y, L1.y, P.z * L2.y));
    w.z = fmaf(P.x, L0.z, fmaf(P.y, L1.z, P.z * L2.z));
    w.w = fmaf(P.x, L0.w, fmaf(P.y, L1.w, fmaf(P.z, L2.w, P.w)));
    return w;
}

__global__ __launch_bounds__(256) void fk_kernel(
    const float* __restrict__ la,    // (B, 3E)
    const float* __restrict__ tip,   // (E,4,4)
    float* __restrict__ out)         // (B, N, 4, 4)
{
    // S is first the deinterleaved tip store (S[3e+row] = tip[e] row), then —
    // after phase B — the world affines (S[3n+row] = world[n] row). 12 KB.
    __shared__ float4 S[NN * 3];
    __shared__ float  laS[3 * EE + 1];

    const int b = blockIdx.x;
    const int t = threadIdx.x;

    // ---- Phase A: cooperative coalesced loads ----
    const float4* tp4 = (const float4*)tip;
    #pragma unroll
    for (int k = 0; k < 4; ++k) {
        const int j = k * NN + t;               // float4 index into (E,4,4)
        if (j < EE * 4) {
            const float4 v = __ldg(tp4 + j);
            const int row = j & 3;
            if (row < 3) S[3 * (j >> 2) + row] = v;
        }
    }
    const float* lab = la + (size_t)b * (3 * EE);
    #pragma unroll
    for (int k = 0; k < 3; ++k) {
        const int j = k * NN + t;
        if (j < 3 * EE) laS[j] = __ldg(lab + j);
    }
    __syncthreads();

    // ---- Phase B: local affine for edge t (node t+1), registers only ----
    float4 L0, L1, L2;
    if (t < EE) {
        const float tha = PI_F * ftanh(laS[3 * t]);
        const float thb = PI_F * ftanh(laS[3 * t + 1]);
        const float thc = PI_F * ftanh(laS[3 * t + 2]);

        float sa, ca, sb, cb, sc, cc;
        __sincosf(tha, &sa, &ca);
        __sincosf(thb, &sb, &cb);
        __sincosf(thc, &sc, &cc);

        // M = Rx(a) * Ry(b) * Rz(c)
        float M[9];
        M[0] = cb * cc;
        M[1] = -cb * sc;
        M[2] = sb;
        M[3] = fmaf(sa * sb, cc, ca * sc);
        M[4] = fmaf(-sa * sb, sc, ca * cc);
        M[5] = -sa * cb;
        M[6] = fmaf(-ca * sb, cc, sa * sc);
        M[7] = fmaf(ca * sb, sc, sa * cc);
        M[8] = ca * cb;

        const float4 T0 = S[3 * t], T1 = S[3 * t + 1], T2 = S[3 * t + 2];
        #define MT(r, D)                                                        \
            D.x = fmaf(M[3*r], T0.x, fmaf(M[3*r+1], T1.x, M[3*r+2] * T2.x));    \
            D.y = fmaf(M[3*r], T0.y, fmaf(M[3*r+1], T1.y, M[3*r+2] * T2.y));    \
            D.z = fmaf(M[3*r], T0.z, fmaf(M[3*r+1], T1.z, M[3*r+2] * T2.z));    \
            D.w = fmaf(M[3*r], T0.w, fmaf(M[3*r+1], T1.w, M[3*r+2] * T2.w));
        MT(0, L0) MT(1, L1) MT(2, L2)
        #undef MT
    }
    __syncthreads();   // all tip reads from S complete; S becomes worlds

    // Seed: node 0 identity (thread 255); nodes 1,2 world = local (threads 0,1).
    if (t == EE) {
        S[0] = make_float4(1.f, 0.f, 0.f, 0.f);
        S[1] = make_float4(0.f, 1.f, 0.f, 0.f);
        S[2] = make_float4(0.f, 0.f, 1.f, 0.f);
    }
    if (t < 2) { S[3 * (t + 1)] = L0; S[3 * (t + 1) + 1] = L1; S[3 * (t + 1) + 2] = L2; }
    __syncthreads();

    // ---- Tree: levels lo = 3,7,15,31,63,127,255 (node n = t+1) ----
    const int n = t + 1;    // thread 255 -> n=256, never active
    #pragma unroll
    for (int lo = 3; lo < NN; lo = 2 * lo + 1) {
        const int hi = (2 * lo + 1 < NN) ? (2 * lo + 1) : NN;
        if (n >= lo && n < hi) {
            const int p = (n - 1) >> 1;
            const float4 P0 = S[3 * p], P1 = S[3 * p + 1], P2 = S[3 * p + 2];
            S[3 * n]     = aff(P0, L0, L1, L2);
            S[3 * n + 1] = aff(P1, L0, L1, L2);
            S[3 * n + 2] = aff(P2, L0, L1, L2);
        }
        __syncthreads();
    }

    // ---- Coalesced output: 16KB CTA block in 4 contiguous rounds ----
    float4* o = (float4*)(out + (size_t)b * NN * 16);
    #pragma unroll
    for (int k = 0; k < 4; ++k) {
        const int j = k * NN + t;
        const int node = j >> 2, row = j & 3;
        float4 v;
        if (row < 3) v = S[3 * node + row];
        else         v = make_float4(0.f, 0.f, 0.f, 1.f);
        o[j] = v;
    }
}

extern "C" void kernel_launch(void* const* d_in, const int* in_sizes, int n_in,
                              void* d_out, int out_size) {
    const float* la  = (const float*)d_in[0];
    const float* tip = (const float*)d_in[1];
    float* out = (float*)d_out;

    const int B = in_sizes[0] / (3 * EE);
    fk_kernel<<<B, NN>>>(la, tip, out);
}

// round 7
// speedup vs baseline: 1.0876x; 1.0876x over previous
#include <cuda_runtime.h>
#include <cuda_bf16.h>

// BodyKinematics tree FK. B=4096, N=256, E=255.
// Round 7: R5 structure (pack prepass + g_tip planes) + TWO batches per CTA
// (tip reuse, halved barrier overhead, 2x ILP) + per-thread level hoisting.

#define NN 256
#define EE 255
#define PI_F 3.14159265358979f

__device__ float4 g_tip[3 * EE];   // [row][edge] planes, lane-coalesced reads

__global__ void pack_kernel(const float* __restrict__ tip) {
    const int j = blockIdx.x * blockDim.x + threadIdx.x;   // float4 index in (E,4,4)
    if (j < EE * 4) {
        const int e = j >> 2, row = j & 3;
        const float4 v = ((const float4*)tip)[j];
        if (row < 3) g_tip[row * EE + e] = v;
    }
}

__device__ __forceinline__ float ftanh(float x) {
    float ax = fabsf(x);
    float t = __expf(2.0f * ax);
    float r = __fdividef(t - 1.0f, t + 1.0f);
    r = ax > 40.0f ? 1.0f : r;
    return copysignf(r, x);
}

__device__ __forceinline__ float4 aff(float4 P, float4 L0, float4 L1, float4 L2) {
    float4 w;
    w.x = fmaf(P.x, L0.x, fmaf(P.y, L1.x, P.z * L2.x));
    w.y = fmaf(P.x, L0.y, fmaf(P.y, L1.y, P.z * L2.y));
    w.z = fmaf(P.x, L0.z, fmaf(P.y, L1.z, P.z * L2.z));
    w.w = fmaf(P.x, L0.w, fmaf(P.y, L1.w, fmaf(P.z, L2.w, P.w)));
    return w;
}

// Build local affine rows for one batch's edge from angles + tip rows.
__device__ __forceinline__ void build_local(
    const float* lap, float4 T0, float4 T1, float4 T2,
    float4& L0, float4& L1, float4& L2)
{
    const float tha = PI_F * ftanh(__ldg(lap));
    const float thb = PI_F * ftanh(__ldg(lap + 1));
    const float thc = PI_F * ftanh(__ldg(lap + 2));

    float sa, ca, sb, cb, sc, cc;
    __sincosf(tha, &sa, &ca);
    __sincosf(thb, &sb, &cb);
    __sincosf(thc, &sc, &cc);

    // M = Rx(a) * Ry(b) * Rz(c)
    float M[9];
    M[0] = cb * cc;
    M[1] = -cb * sc;
    M[2] = sb;
    M[3] = fmaf(sa * sb, cc, ca * sc);
    M[4] = fmaf(-sa * sb, sc, ca * cc);
    M[5] = -sa * cb;
    M[6] = fmaf(-ca * sb, cc, sa * sc);
    M[7] = fmaf(ca * sb, sc, sa * cc);
    M[8] = ca * cb;

    #define MT(r, D)                                                        \
        D.x = fmaf(M[3*r], T0.x, fmaf(M[3*r+1], T1.x, M[3*r+2] * T2.x));    \
        D.y = fmaf(M[3*r], T0.y, fmaf(M[3*r+1], T1.y, M[3*r+2] * T2.y));    \
        D.z = fmaf(M[3*r], T0.z, fmaf(M[3*r+1], T1.z, M[3*r+2] * T2.z));    \
        D.w = fmaf(M[3*r], T0.w, fmaf(M[3*r+1], T1.w, M[3*r+2] * T2.w));
    MT(0, L0) MT(1, L1) MT(2, L2)
    #undef MT
}

__global__ __launch_bounds__(256) void fk_kernel(
    const float* __restrict__ la,    // (B, 3E)
    float* __restrict__ out)         // (B, N, 4, 4)
{
    __shared__ float4 S0[NN * 3];    // worlds, batch b0 (12 KB)
    __shared__ float4 S1[NN * 3];    // worlds, batch b1 (12 KB)

    const int b0 = 2 * blockIdx.x;
    const int t = threadIdx.x;

    float4 A0, A1, A2;   // locals, batch b0, edge t
    float4 B0, B1, B2;   // locals, batch b1, edge t

    if (t < EE) {
        const float4 T0 = g_tip[t];
        const float4 T1 = g_tip[EE + t];
        const float4 T2 = g_tip[2 * EE + t];
        const float* lap0 = la + (size_t)b0 * (3 * EE) + 3 * t;
        build_local(lap0,            T0, T1, T2, A0, A1, A2);
        build_local(lap0 + 3 * EE,   T0, T1, T2, B0, B1, B2);
    }

    // Seeds: node 0 identity; nodes 1,2 world = local (level-1 done here).
    if (t == EE) {
        const float4 i0 = make_float4(1.f, 0.f, 0.f, 0.f);
        const float4 i1 = make_float4(0.f, 1.f, 0.f, 0.f);
        const float4 i2 = make_float4(0.f, 0.f, 1.f, 0.f);
        S0[0] = i0; S0[1] = i1; S0[2] = i2;
        S1[0] = i0; S1[1] = i1; S1[2] = i2;
    }
    if (t < 2) {
        const int q = 3 * (t + 1);
        S0[q] = A0; S0[q + 1] = A1; S0[q + 2] = A2;
        S1[q] = B0; S1[q + 1] = B1; S1[q + 2] = B2;
    }
    __syncthreads();

    // Per-thread constants: node, its single active level, smem offsets.
    const int n   = t + 1;                          // t==EE -> inactive
    const int lvl = (t == EE) ? 0 : (31 - __clz(n + 1));  // node n is in level lvl
    const int i3  = 3 * n;
    const int p3  = 3 * ((n - 1) >> 1);

    // Levels k=2..8 (nodes 3..255). Each thread computes at exactly one k.
    #pragma unroll
    for (int k = 2; k <= 8; ++k) {
        if (lvl == k) {
            const float4 P0 = S0[p3], P1 = S0[p3 + 1], P2 = S0[p3 + 2];
            S0[i3]     = aff(P0, A0, A1, A2);
            S0[i3 + 1] = aff(P1, A0, A1, A2);
            S0[i3 + 2] = aff(P2, A0, A1, A2);
            const float4 Q0 = S1[p3], Q1 = S1[p3 + 1], Q2 = S1[p3 + 2];
            S1[i3]     = aff(Q0, B0, B1, B2);
            S1[i3 + 1] = aff(Q1, B0, B1, B2);
            S1[i3 + 2] = aff(Q2, B0, B1, B2);
        }
        __syncthreads();
    }

    // Coalesced output: 32 KB (two adjacent batch blocks), 8 contiguous rounds.
    float4* o = (float4*)(out + (size_t)b0 * NN * 16);
    const float4 r3 = make_float4(0.f, 0.f, 0.f, 1.f);
    #pragma unroll
    for (int k = 0; k < 4; ++k) {
        const int j = k * NN + t;
        const int node = j >> 2, row = j & 3;
        o[j] = (row < 3) ? S0[3 * node + row] : r3;
    }
    #pragma unroll
    for (int k = 0; k < 4; ++k) {
        const int j = k * NN + t;
        const int node = j >> 2, row = j & 3;
        o[4 * NN + j] = (row < 3) ? S1[3 * node + row] : r3;
    }
}

extern "C" void kernel_launch(void* const* d_in, const int* in_sizes, int n_in,
                              void* d_out, int out_size) {
    const float* la  = (const float*)d_in[0];
    const float* tip = (const float*)d_in[1];
    float* out = (float*)d_out;

    const int B = in_sizes[0] / (3 * EE);
    pack_kernel<<<4, 256>>>(tip);
    fk_kernel<<<B / 2, NN>>>(la, out);
}